// round 11
// baseline (speedup 1.0000x reference)
#include <cuda_runtime.h>
#include <cuda_fp16.h>
#include <mma.h>
#include <cstdint>

using namespace nvcuda;

__device__ __forceinline__ float2 cmul(float2 a, float2 b) {
    return make_float2(fmaf(a.x, b.x, -a.y * b.y), fmaf(a.x, b.y, a.y * b.x));
}

// Cody-Waite reduction to ~[-pi, pi]; exact for |ph| <~ 25000
__device__ __forceinline__ float red2pi(float ph) {
    float q = rintf(ph * 0.15915494309f);
    ph = fmaf(q, -6.28125f, ph);
    ph = fmaf(q, -1.93530717e-3f, ph);
    return ph;
}

// ============================ WMMA kernel ============================
// Grid = 2*H, CTA = 64 threads (2 warps). CTA b handles head h = b>>1 and
// M-half mh = b&1 (rows i = 32*mh .. 32*mh+31 of the per-head GEMM).
//   out[h, 64j+i] = sum_n 2*Re(Cd * E^i * W^j),  E = exp(dtA), W = E^64.
// Real GEMM M=32 x N=32 x K=64 per CTA, k-interleaved (k=2n Re, k=2n+1 Im);
// B holds powers of conj(W); x2 folded into Cd. Single-pass fp16 (measured
// rel_err ~2.3e-4 at this precision, under the 1e-3 gate).
// Per-warp redundant constants in registers -> no const smem, ONE barrier.
// Small CTAs (~14/SM) give cross-CTA phase diversity to hide latency chains.

static constexpr int LDA = 72;   // fp16 elems; 144 B rows, 16B-aligned

__global__ __launch_bounds__(64)
void s4d_wmma(const float* __restrict__ log_dt,
              const float* __restrict__ Cr,
              const float* __restrict__ logAre,
              const float* __restrict__ Aimag,
              float* __restrict__ out)
{
    __shared__ __half Am[32 * LDA];     // 4608 B
    __shared__ __half Bm[32 * LDA];     // 4608 B

    const int h   = blockIdx.x >> 1;
    const int mh  = blockIdx.x & 1;
    const int tid = threadIdx.x;
    const int wid = tid >> 5;           // 0 or 1
    const int n   = tid & 31;           // lane = mode

    // ---- per-warp constants (lane n = mode n), all in registers ----
    const float dt  = __expf(log_dt[h]);
    const float Are = -__expf(logAre[h * 32 + n]);
    const float Ai  = Aimag[h * 32 + n];
    const float dre = Are * dt;
    const float dim = Ai * dt;                  // |dim| <= ~9.8

    float sn, cs;
    __sincosf(dim, &sn, &cs);
    const float e1 = __expf(dre);
    const float2 E = make_float2(e1 * cs, e1 * sn);
    const float inv = __frcp_rn(fmaf(Are, Are, Ai * Ai));
    const float ccre = Cr[(h * 32 + n) * 2 + 0];
    const float ccim = Cr[(h * 32 + n) * 2 + 1];
    const float numre = E.x - 1.0f, numim = E.y;
    const float tre = ccre * numre - ccim * numim;
    const float tim = ccre * numim + ccim * numre;
    const float2 Cd = make_float2(2.0f * (tre * Are + tim * Ai) * inv,
                                  2.0f * (tim * Are - tre * Ai) * inv);

    const float2 E2  = cmul(E, E);
    const float2 E4  = cmul(E2, E2);
    const float2 E8  = cmul(E4, E4);
    const float2 E16 = cmul(E8, E8);
    const float2 E32 = cmul(E16, E16);

    // Wc = conj(exp(64*dtA)) computed directly (log-depth, independent of E-chain)
    const float ph = red2pi(dim * 64.0f);       // |arg| <= ~630, exact CW range
    float snT, csT;
    __sincosf(ph, &snT, &csT);
    const float eT = __expf(dre * 64.0f);       // >= e^-3.2
    const float2 Wc   = make_float2(eT * csT, -eT * snT);
    const float2 Wc2  = cmul(Wc, Wc);
    const float2 Wc4  = cmul(Wc2, Wc2);
    const float2 Wc8  = cmul(Wc4, Wc4);
    const float2 Wc16 = cmul(Wc8, Wc8);

    // ---- gen A: local rows r = 16*wid .. 16*wid+15, global i = 32*mh + r ----
    {
        float2 base = Cd;                        // 2*Cd * E^(32*mh + 16*wid)
        if (wid) base = cmul(base, E16);
        if (mh)  base = cmul(base, E32);
        float2 z[16];
        z[0] = base;
        z[1] = cmul(base, E);
        z[2] = cmul(base, E2);
        z[4] = cmul(base, E4);
        z[3] = cmul(z[1], E2);
        z[5] = cmul(z[1], E4);
        z[6] = cmul(z[2], E4);
        z[7] = cmul(z[3], E4);
        #pragma unroll
        for (int s = 0; s < 8; s++) z[8 + s] = cmul(z[s], E8);
        #pragma unroll
        for (int s = 0; s < 16; s++) {
            const int r = wid * 16 + s;
            ((__half2*)(Am + r * LDA))[n] = __floats2half2_rn(z[s].x, z[s].y);
        }
    }

    // ---- gen B: cols j = 16*wid .. 16*wid+15 (conj(W)^j) ----
    {
        float2 base = make_float2(1.0f, 0.0f);
        if (wid) base = Wc16;
        float2 w[16];
        w[0] = base;
        w[1] = cmul(base, Wc);
        w[2] = cmul(base, Wc2);
        w[4] = cmul(base, Wc4);
        w[3] = cmul(w[1], Wc2);
        w[5] = cmul(w[1], Wc4);
        w[6] = cmul(w[2], Wc4);
        w[7] = cmul(w[3], Wc4);
        #pragma unroll
        for (int s = 0; s < 8; s++) w[8 + s] = cmul(w[s], Wc8);
        #pragma unroll
        for (int s = 0; s < 16; s++) {
            const int j = wid * 16 + s;
            ((__half2*)(Bm + j * LDA))[n] = __floats2half2_rn(w[s].x, w[s].y);
        }
    }
    __syncthreads();

    // ---- WMMA: warp wid owns local m-tile (rows 16*wid..+15), loops jt ----
    {
        wmma::fragment<wmma::matrix_a, 16, 16, 16, __half, wmma::row_major> af[4];
        #pragma unroll
        for (int kt = 0; kt < 4; kt++)
            wmma::load_matrix_sync(af[kt], Am + (wid * 16) * LDA + kt * 16, LDA);

        #pragma unroll
        for (int jt = 0; jt < 2; jt++) {
            wmma::fragment<wmma::matrix_b, 16, 16, 16, __half, wmma::col_major> bf;
            wmma::fragment<wmma::accumulator, 16, 16, 16, float> acc;
            wmma::fill_fragment(acc, 0.0f);
            #pragma unroll
            for (int kt = 0; kt < 4; kt++) {
                wmma::load_matrix_sync(bf, Bm + (jt * 16) * LDA + kt * 16, LDA);
                wmma::mma_sync(acc, af[kt], bf, acc);
            }
            // element (i, j) -> out[h*2048 + j*64 + i], i = 32*mh + 16*wid + ...
            float* op = out + (size_t)h * 2048 + (size_t)(jt * 16) * 64
                        + mh * 32 + wid * 16;
            wmma::store_matrix_sync(op, acc, 64, wmma::mem_col_major);
        }
    }
}

// ---------------- generic fallback (any H, N2, L) ----------------
__global__ void s4d_fallback(
    const float* __restrict__ log_dt,
    const float* __restrict__ Cr,
    const float* __restrict__ logAre,
    const float* __restrict__ Aimag,
    float* __restrict__ out, int H, int N2, int L)
{
    const long long idx = (long long)blockIdx.x * blockDim.x + threadIdx.x;
    if (idx >= (long long)H * L) return;
    const int h = (int)(idx / L);
    const int l = (int)(idx % L);
    const float dt = __expf(log_dt[h]);
    const float lf = (float)l;
    float acc = 0.0f;
    for (int n = 0; n < N2; n++) {
        const float Are = -__expf(logAre[h * N2 + n]);
        const float Ai  = Aimag[h * N2 + n];
        const float dre = Are * dt;
        const float dim = Ai * dt;
        float s1, c1;
        __sincosf(dim, &s1, &c1);
        const float e1 = __expf(dre);
        const float numre = fmaf(e1, c1, -1.0f);
        const float numim = e1 * s1;
        const float inv  = __frcp_rn(fmaf(Are, Are, Ai * Ai));
        const float ccre = Cr[(h * N2 + n) * 2 + 0];
        const float ccim = Cr[(h * N2 + n) * 2 + 1];
        const float tre = ccre * numre - ccim * numim;
        const float tim = ccre * numim + ccim * numre;
        const float cdre = (tre * Are + tim * Ai) * inv;
        const float cdim = (tim * Are - tre * Ai) * inv;
        const float ph = red2pi(dim * lf);
        float s, c;
        __sincosf(ph, &s, &c);
        const float r = __expf(dre * lf);
        acc += r * (cdre * c - cdim * s);
    }
    out[idx] = 2.0f * acc;
}

extern "C" void kernel_launch(void* const* d_in, const int* in_sizes, int n_in,
                              void* d_out, int out_size)
{
    const float* log_dt = (const float*)d_in[0];
    const float* Cr     = (const float*)d_in[1];
    const float* lar    = (const float*)d_in[2];
    const float* aim    = (const float*)d_in[3];
    float* out = (float*)d_out;

    const int H  = in_sizes[0];
    const int N2 = (H > 0) ? in_sizes[2] / H : 0;
    const int L  = (H > 0) ? out_size / H : 0;

    if (N2 == 32 && L == 2048) {
        s4d_wmma<<<H * 2, 64>>>(log_dt, Cr, lar, aim, out);
    } else {
        const long long total = (long long)H * L;
        const int blocks = (int)((total + 127) / 128);
        s4d_fallback<<<blocks, 128>>>(log_dt, Cr, lar, aim, out, H, N2, L);
    }
}

// round 12
// speedup vs baseline: 1.0156x; 1.0156x over previous
#include <cuda_runtime.h>
#include <cuda_fp16.h>
#include <mma.h>
#include <cstdint>

using namespace nvcuda;

__device__ __forceinline__ float2 cmul(float2 a, float2 b) {
    return make_float2(fmaf(a.x, b.x, -a.y * b.y), fmaf(a.x, b.y, a.y * b.x));
}

// Cody-Waite reduction to ~[-pi, pi]; exact for |ph| <~ 25000
__device__ __forceinline__ float red2pi(float ph) {
    float q = rintf(ph * 0.15915494309f);
    ph = fmaf(q, -6.28125f, ph);
    ph = fmaf(q, -1.93530717e-3f, ph);
    return ph;
}

// ============================ WMMA kernel (transposed) ============================
// One CTA (128 thr, 4 warps) per head h.  l = 64j + i, j in [0,32), i in [0,64).
//   out[h, 64j+i] = sum_n [ ReW^j * 2ReP  -  ImW^j * 2ImP ],  P = Cd*E^i, W = E^64.
// GEMM D[j][i] = A'[32j x 64k] * B'[64k x 64i], k-interleaved (k=2n Re, 2n+1 Im):
//   A'[j][2n] = Re W^j,  A'[j][2n+1] = Im W^j          (row-major)
//   B'[2n][i] = 2 Re P,  B'[2n+1][i] = -2 Im P         (stored col-major)
// B' values = conj(2Cd * E^i), generated with conjugated constants (free).
// D is row-major in gmem (ld = 64)  ->  paired contiguous stores, no staging.
// Single-pass fp16 (measured rel_err 2.3e-4 at this precision).
// Per-warp redundant register constants; ONE barrier; 7 CTAs/SM -> one wave.

static constexpr int LDA = 72;   // fp16 elems; 144 B rows, 16B-aligned

__global__ __launch_bounds__(128, 7)
void s4d_wmma(const float* __restrict__ log_dt,
              const float* __restrict__ Cr,
              const float* __restrict__ logAre,
              const float* __restrict__ Aimag,
              float* __restrict__ out)
{
    __shared__ __half Asm[32 * LDA];    // W-powers,  4608 B
    __shared__ __half Bsm[64 * LDA];    // P-values,  9216 B  -> 13824 B total

    const int h   = blockIdx.x;
    const int tid = threadIdx.x;
    const int wid = tid >> 5;           // 0..3
    const int n   = tid & 31;           // lane = mode

    // ---- per-lane constants (redundant per warp, all registers) ----
    const float dt  = __expf(log_dt[h]);
    const float Are = -__expf(logAre[h * 32 + n]);
    const float Ai  = Aimag[h * 32 + n];
    const float dre = Are * dt;
    const float dim = Ai * dt;                  // |dim| <= ~9.8

    float sn, cs;
    __sincosf(dim, &sn, &cs);
    const float e1 = __expf(dre);
    const float2 E = make_float2(e1 * cs, e1 * sn);
    const float inv = __frcp_rn(fmaf(Are, Are, Ai * Ai));
    const float ccre = Cr[(h * 32 + n) * 2 + 0];
    const float ccim = Cr[(h * 32 + n) * 2 + 1];
    const float numre = E.x - 1.0f, numim = E.y;
    const float tre = ccre * numre - ccim * numim;
    const float tim = ccre * numim + ccim * numre;
    // conj(2*Cd):
    const float2 Cdc2 = make_float2( 2.0f * (tre * Are + tim * Ai) * inv,
                                    -2.0f * (tim * Are - tre * Ai) * inv);
    // conj(E) and its powers (for B' = conj(2Cd * E^i)):
    const float2 Ec   = make_float2(E.x, -E.y);
    const float2 Ec2  = cmul(Ec, Ec);
    const float2 Ec4  = cmul(Ec2, Ec2);
    const float2 Ec8  = cmul(Ec4, Ec4);
    const float2 Ec16 = cmul(Ec8, Ec8);
    const float2 Ec32 = cmul(Ec16, Ec16);

    // W = exp(64*dtA) direct; powers for A'
    const float ph = red2pi(dim * 64.0f);       // |arg| <= ~630, exact CW range
    float snT, csT;
    __sincosf(ph, &snT, &csT);
    const float eT = __expf(dre * 64.0f);       // >= e^-3.2
    const float2 W   = make_float2(eT * csT, eT * snT);
    const float2 W2  = cmul(W, W);
    const float2 W4  = cmul(W2, W2);
    const float2 W8  = cmul(W4, W4);
    const float2 W16 = cmul(W8, W8);

    // ---- gen A': rows j = 8*wid .. 8*wid+7  (W^j) ----
    {
        float2 base = make_float2(1.0f, 0.0f);   // W^(8*wid)
        if (wid & 1) base = W8;
        if (wid & 2) base = cmul(base, W16);
        float2 z[8];
        z[0] = base;
        z[1] = cmul(base, W);
        z[2] = cmul(base, W2);
        z[4] = cmul(base, W4);
        z[3] = cmul(z[1], W2);
        z[5] = cmul(z[1], W4);
        z[6] = cmul(z[2], W4);
        z[7] = cmul(z[3], W4);
        #pragma unroll
        for (int s = 0; s < 8; s++) {
            const int j = wid * 8 + s;
            ((__half2*)(Asm + j * LDA))[n] = __floats2half2_rn(z[s].x, z[s].y);
        }
    }

    // ---- gen B': cols i = 16*wid .. 16*wid+15  (conj(2Cd * E^i)) ----
    {
        float2 base = Cdc2;                      // conj(2Cd) * Ec^(16*wid)
        if (wid & 1) base = cmul(base, Ec16);
        if (wid & 2) base = cmul(base, Ec32);
        float2 z[16];
        z[0] = base;
        z[1] = cmul(base, Ec);
        z[2] = cmul(base, Ec2);
        z[4] = cmul(base, Ec4);
        z[3] = cmul(z[1], Ec2);
        z[5] = cmul(z[1], Ec4);
        z[6] = cmul(z[2], Ec4);
        z[7] = cmul(z[3], Ec4);
        #pragma unroll
        for (int s = 0; s < 8; s++) z[8 + s] = cmul(z[s], Ec8);
        #pragma unroll
        for (int s = 0; s < 16; s++) {
            const int i = wid * 16 + s;
            ((__half2*)(Bsm + i * LDA))[n] = __floats2half2_rn(z[s].x, z[s].y);
        }
    }
    __syncthreads();

    // ---- WMMA: warp wid owns i-tile it=wid; loop jt = 0,1 over j-tiles ----
    {
        const int it = wid;
        wmma::fragment<wmma::matrix_b, 16, 16, 16, __half, wmma::col_major> bf[4];
        #pragma unroll
        for (int kt = 0; kt < 4; kt++)
            wmma::load_matrix_sync(bf[kt], Bsm + (it * 16) * LDA + kt * 16, LDA);

        #pragma unroll
        for (int jt = 0; jt < 2; jt++) {
            wmma::fragment<wmma::matrix_a, 16, 16, 16, __half, wmma::row_major> af;
            wmma::fragment<wmma::accumulator, 16, 16, 16, float> acc;
            wmma::fill_fragment(acc, 0.0f);
            #pragma unroll
            for (int kt = 0; kt < 4; kt++) {
                wmma::load_matrix_sync(af, Asm + (jt * 16) * LDA + kt * 16, LDA);
                wmma::mma_sync(acc, af, bf[kt], acc);
            }
            // D[j][i] -> out[h*2048 + j*64 + i], row-major, ld = 64
            float* op = out + (size_t)h * 2048 + (size_t)(jt * 16) * 64 + it * 16;
            wmma::store_matrix_sync(op, acc, 64, wmma::mem_row_major);
        }
    }
}

// ---------------- generic fallback (any H, N2, L) ----------------
__global__ void s4d_fallback(
    const float* __restrict__ log_dt,
    const float* __restrict__ Cr,
    const float* __restrict__ logAre,
    const float* __restrict__ Aimag,
    float* __restrict__ out, int H, int N2, int L)
{
    const long long idx = (long long)blockIdx.x * blockDim.x + threadIdx.x;
    if (idx >= (long long)H * L) return;
    const int h = (int)(idx / L);
    const int l = (int)(idx % L);
    const float dt = __expf(log_dt[h]);
    const float lf = (float)l;
    float acc = 0.0f;
    for (int n = 0; n < N2; n++) {
        const float Are = -__expf(logAre[h * N2 + n]);
        const float Ai  = Aimag[h * N2 + n];
        const float dre = Are * dt;
        const float dim = Ai * dt;
        float s1, c1;
        __sincosf(dim, &s1, &c1);
        const float e1 = __expf(dre);
        const float numre = fmaf(e1, c1, -1.0f);
        const float numim = e1 * s1;
        const float inv  = __frcp_rn(fmaf(Are, Are, Ai * Ai));
        const float ccre = Cr[(h * N2 + n) * 2 + 0];
        const float ccim = Cr[(h * N2 + n) * 2 + 1];
        const float tre = ccre * numre - ccim * numim;
        const float tim = ccre * numim + ccim * numre;
        const float cdre = (tre * Are + tim * Ai) * inv;
        const float cdim = (tim * Are - tre * Ai) * inv;
        const float ph = red2pi(dim * lf);
        float s, c;
        __sincosf(ph, &s, &c);
        const float r = __expf(dre * lf);
        acc += r * (cdre * c - cdim * s);
    }
    out[idx] = 2.0f * acc;
}

extern "C" void kernel_launch(void* const* d_in, const int* in_sizes, int n_in,
                              void* d_out, int out_size)
{
    const float* log_dt = (const float*)d_in[0];
    const float* Cr     = (const float*)d_in[1];
    const float* lar    = (const float*)d_in[2];
    const float* aim    = (const float*)d_in[3];
    float* out = (float*)d_out;

    const int H  = in_sizes[0];
    const int N2 = (H > 0) ? in_sizes[2] / H : 0;
    const int L  = (H > 0) ? out_size / H : 0;

    if (N2 == 32 && L == 2048) {
        s4d_wmma<<<H, 128>>>(log_dt, Cr, lar, aim, out);
    } else {
        const long long total = (long long)H * L;
        const int blocks = (int)((total + 127) / 128);
        s4d_fallback<<<blocks, 128>>>(log_dt, Cr, lar, aim, out, H, N2, L);
    }
}